// round 11
// baseline (speedup 1.0000x reference)
#include <cuda_runtime.h>
#include <stdint.h>

#define NUM_BINS 256
#define NCH_SAMPLE 3
#define NCH_TOTAL 6
#define NPX (2048 * 4096)

#define SLICES 246                  // slices per channel
#define NCTAS (SLICES * 3)          // 738 CTAs (<= 148 SMs * 5 resident = 740)
#define GPC 8526                    // float4 groups per CTA: ceil(2097152/246)
#define SMEM_BYTES (GPC * 4)        // 34104 B dynamic smem for packed bins

// Static device scratch (zeroed at load; last-done CTA restores zeros each
// run, so graph replays are deterministic).
__device__ int g_hist[NCH_SAMPLE][NUM_BINS];
__device__ int g_ticket[NCH_SAMPLE];
__device__ int g_done;

// Single persistent kernel:
//  A: hist + binize own sample slice (bins kept in dynamic smem)
//  B: grid-stride copy of target channels (hides the per-channel hist sync)
//  C: spin on own channel's ticket, build the LUT
//  D: apply LUT from smem bins -> output
__global__ void __launch_bounds__(256, 5)
equalize_fused_kernel(const float* __restrict__ img,
                      float* __restrict__ out, int npx) {
    const int t = threadIdx.x;
    const int c  = blockIdx.x % NCH_SAMPLE;     // channel
    const int sl = blockIdx.x / NCH_SAMPLE;     // slice within channel
    const int n4 = npx >> 2;
    const int base = sl * GPC;
    const int end  = min(base + GPC, n4);

    extern __shared__ uint32_t s_bins[];        // GPC packed bins (dynamic)
    __shared__ int   s_hist[4][NUM_BINS];       // 4 KB replicas / scan scratch
    __shared__ float s_lut[NUM_BINS];           // 1 KB
    __shared__ int   s_lastnz;

    // ---- Phase A: hist + binize (sample read happens exactly once) ----
    for (int i = t; i < 4 * NUM_BINS; i += blockDim.x) ((int*)s_hist)[i] = 0;
    __syncthreads();

    {
        const float4* p = (const float4*)(img + (size_t)c * npx);
        const int sub = t & 3;
        #pragma unroll 4
        for (int g = base + t; g < end; g += 256) {
            float4 v = __ldcs(&p[g]);
            int b0 = min(NUM_BINS - 1, max(0, (int)v.x));
            int b1 = min(NUM_BINS - 1, max(0, (int)v.y));
            int b2 = min(NUM_BINS - 1, max(0, (int)v.z));
            int b3 = min(NUM_BINS - 1, max(0, (int)v.w));
            s_bins[g - base] = (uint32_t)b0 | ((uint32_t)b1 << 8) |
                               ((uint32_t)b2 << 16) | ((uint32_t)b3 << 24);
            atomicAdd(&s_hist[sub][b0], 1);
            atomicAdd(&s_hist[sub][b1], 1);
            atomicAdd(&s_hist[sub][b2], 1);
            atomicAdd(&s_hist[sub][b3], 1);
        }
    }
    __syncthreads();
    {
        int s = s_hist[0][t] + s_hist[1][t] + s_hist[2][t] + s_hist[3][t];
        if (s) atomicAdd(&g_hist[c][t], s);
    }
    __threadfence();                            // release hist before arrive
    if (t == 0) atomicAdd(&g_ticket[c], 1);

    // ---- Phase B: target copy (overlaps / hides the hist sync) ----
    {
        const float4* p = (const float4*)(img + (size_t)NCH_SAMPLE * npx);
        float4*       q = (float4*)(out + (size_t)NCH_SAMPLE * npx);
        const int tn4 = NCH_SAMPLE * n4;
        const int stride = NCTAS * 256;
        int i = blockIdx.x * 256 + t;
        for (; i + stride < tn4; i += 2 * stride) {
            float4 a = __ldcs(&p[i]);
            float4 d = __ldcs(&p[i + stride]);
            __stcs(&q[i], a);
            __stcs(&q[i + stride], d);
        }
        if (i < tn4) __stcs(&q[i], __ldcs(&p[i]));
    }

    // ---- Phase C: wait for own channel's arrivals, build the LUT ----
    if (t == 0) {
        while (*(volatile int*)&g_ticket[c] != SLICES) __nanosleep(64);
    }
    __syncthreads();
    __threadfence();

    {
        int* hist = s_hist[0];
        int* cum  = s_hist[1];
        int h = __ldcg(&g_hist[c][t]);
        hist[t] = h;
        cum[t]  = h;
        if (t == 0) s_lastnz = 0;
        __syncthreads();

        #pragma unroll
        for (int off = 1; off < NUM_BINS; off <<= 1) {
            int tmp = (t >= off) ? cum[t - off] : 0;
            __syncthreads();
            cum[t] += tmp;
            __syncthreads();
        }
        if (h > 0) atomicMax(&s_lastnz, t);
        __syncthreads();

        const int total = cum[NUM_BINS - 1];
        const int step  = (total - hist[s_lastnz]) / (NUM_BINS - 1);

        float outv;
        if (step == 0) {
            outv = (float)t;                    // identity when step==0
        } else {
            int l = (t == 0) ? 0 : (cum[t - 1] + (step >> 1)) / step;
            outv = (float)min(NUM_BINS - 1, max(0, l));
        }
        s_lut[t] = outv;
        __syncthreads();
    }

    // ---- Phase D: apply from smem bins (no global re-read of samples) ----
    {
        float4* q = (float4*)(out + (size_t)c * npx);
        #pragma unroll 4
        for (int g = base + t; g < end; g += 256) {
            uint32_t w = s_bins[g - base];
            float4 r;
            r.x = s_lut[w & 255];
            r.y = s_lut[(w >> 8) & 255];
            r.z = s_lut[(w >> 16) & 255];
            r.w = s_lut[w >> 24];
            __stcs(&q[g], r);
        }
    }

    // ---- reset shared state for next graph replay (last-done CTA) ----
    __syncthreads();
    __shared__ int s_last;
    if (t == 0) {
        int d = atomicAdd(&g_done, 1);
        s_last = (d == NCTAS - 1);
    }
    __syncthreads();
    if (s_last) {
        g_hist[0][t] = 0;
        g_hist[1][t] = 0;
        g_hist[2][t] = 0;
        if (t == 0) {
            g_ticket[0] = 0; g_ticket[1] = 0; g_ticket[2] = 0;
            g_done = 0;
        }
    }
}

extern "C" void kernel_launch(void* const* d_in, const int* in_sizes, int n_in,
                              void* d_out, int out_size) {
    const float* img = (const float*)d_in[0];
    float* out = (float*)d_out;
    const int npx = in_sizes[0] / NCH_TOTAL;   // 2048*4096

    cudaFuncSetAttribute(equalize_fused_kernel,
                         cudaFuncAttributeMaxDynamicSharedMemorySize,
                         SMEM_BYTES);
    equalize_fused_kernel<<<NCTAS, 256, SMEM_BYTES>>>(img, out, npx);
}

// round 12
// speedup vs baseline: 1.1897x; 1.1897x over previous
#include <cuda_runtime.h>
#include <stdint.h>

#define NUM_BINS 256
#define NCH_SAMPLE 3
#define NCH_TOTAL 6
#define NPX (2048 * 4096)

#define SLICES 197                 // slices per channel
#define NCTAS (SLICES * 3)         // 591 CTAs total (<= 148 SMs * 4 resident)
#define GPC 10646                  // float4 groups per CTA: ceil(2097152/197)

// Static device scratch (zeroed at load; last-done CTA restores zeros each
// run, so graph replays are deterministic).
__device__ int g_hist[NCH_SAMPLE][NUM_BINS];
__device__ int g_ticket;
__device__ int g_done;

// Single persistent kernel (R10 structure, loads front-batched 4x for MLP):
//  A: hist + binize own sample slice (bins kept in smem)
//  B: grid-stride copy of target channels (hides the hist sync)
//  C: spin on ticket, build own channel's LUT
//  D: apply LUT from smem bins -> output
__global__ void __launch_bounds__(256, 4)
equalize_fused_kernel(const float* __restrict__ img,
                      float* __restrict__ out, int npx) {
    const int t = threadIdx.x;
    const int c  = blockIdx.x % NCH_SAMPLE;     // channel
    const int sl = blockIdx.x / NCH_SAMPLE;     // slice within channel
    const int n4 = npx >> 2;
    const int base = sl * GPC;
    const int end  = min(base + GPC, n4);

    __shared__ uint32_t s_bins[GPC];            // 42584 B packed bins
    __shared__ int      s_hist[4][NUM_BINS];    // 4 KB replicas / scan scratch
    __shared__ float    s_lut[NUM_BINS];        // 1 KB
    __shared__ int      s_lastnz;

    // ---- Phase A: hist + binize (sample read happens exactly once) ----
    for (int i = t; i < 4 * NUM_BINS; i += blockDim.x) ((int*)s_hist)[i] = 0;
    __syncthreads();

    {
        const float4* p = (const float4*)(img + (size_t)c * npx);
        const int sub = t & 3;
        int g = base + t;
        for (; g + 768 < end; g += 1024) {
            float4 v0 = __ldcs(&p[g]);
            float4 v1 = __ldcs(&p[g + 256]);
            float4 v2 = __ldcs(&p[g + 512]);
            float4 v3 = __ldcs(&p[g + 768]);

            int a0 = min(255, max(0, (int)v0.x)), a1 = min(255, max(0, (int)v0.y));
            int a2 = min(255, max(0, (int)v0.z)), a3 = min(255, max(0, (int)v0.w));
            int b0 = min(255, max(0, (int)v1.x)), b1 = min(255, max(0, (int)v1.y));
            int b2 = min(255, max(0, (int)v1.z)), b3 = min(255, max(0, (int)v1.w));
            int c0 = min(255, max(0, (int)v2.x)), c1 = min(255, max(0, (int)v2.y));
            int c2 = min(255, max(0, (int)v2.z)), c3 = min(255, max(0, (int)v2.w));
            int d0 = min(255, max(0, (int)v3.x)), d1 = min(255, max(0, (int)v3.y));
            int d2 = min(255, max(0, (int)v3.z)), d3 = min(255, max(0, (int)v3.w));

            s_bins[g - base]       = (uint32_t)a0 | ((uint32_t)a1 << 8) |
                                     ((uint32_t)a2 << 16) | ((uint32_t)a3 << 24);
            s_bins[g - base + 256] = (uint32_t)b0 | ((uint32_t)b1 << 8) |
                                     ((uint32_t)b2 << 16) | ((uint32_t)b3 << 24);
            s_bins[g - base + 512] = (uint32_t)c0 | ((uint32_t)c1 << 8) |
                                     ((uint32_t)c2 << 16) | ((uint32_t)c3 << 24);
            s_bins[g - base + 768] = (uint32_t)d0 | ((uint32_t)d1 << 8) |
                                     ((uint32_t)d2 << 16) | ((uint32_t)d3 << 24);

            atomicAdd(&s_hist[sub][a0], 1); atomicAdd(&s_hist[sub][a1], 1);
            atomicAdd(&s_hist[sub][a2], 1); atomicAdd(&s_hist[sub][a3], 1);
            atomicAdd(&s_hist[sub][b0], 1); atomicAdd(&s_hist[sub][b1], 1);
            atomicAdd(&s_hist[sub][b2], 1); atomicAdd(&s_hist[sub][b3], 1);
            atomicAdd(&s_hist[sub][c0], 1); atomicAdd(&s_hist[sub][c1], 1);
            atomicAdd(&s_hist[sub][c2], 1); atomicAdd(&s_hist[sub][c3], 1);
            atomicAdd(&s_hist[sub][d0], 1); atomicAdd(&s_hist[sub][d1], 1);
            atomicAdd(&s_hist[sub][d2], 1); atomicAdd(&s_hist[sub][d3], 1);
        }
        for (; g < end; g += 256) {
            float4 v = __ldcs(&p[g]);
            int b0 = min(255, max(0, (int)v.x));
            int b1 = min(255, max(0, (int)v.y));
            int b2 = min(255, max(0, (int)v.z));
            int b3 = min(255, max(0, (int)v.w));
            s_bins[g - base] = (uint32_t)b0 | ((uint32_t)b1 << 8) |
                               ((uint32_t)b2 << 16) | ((uint32_t)b3 << 24);
            atomicAdd(&s_hist[sub][b0], 1);
            atomicAdd(&s_hist[sub][b1], 1);
            atomicAdd(&s_hist[sub][b2], 1);
            atomicAdd(&s_hist[sub][b3], 1);
        }
    }
    __syncthreads();
    {
        int s = s_hist[0][t] + s_hist[1][t] + s_hist[2][t] + s_hist[3][t];
        if (s) atomicAdd(&g_hist[c][t], s);
    }
    __threadfence();                            // release hist before arrive
    if (t == 0) atomicAdd(&g_ticket, 1);

    // ---- Phase B: target copy (overlaps / hides the hist sync) ----
    {
        const float4* p = (const float4*)(img + (size_t)NCH_SAMPLE * npx);
        float4*       q = (float4*)(out + (size_t)NCH_SAMPLE * npx);
        const int tn4 = NCH_SAMPLE * n4;
        const int stride = NCTAS * 256;
        int i = blockIdx.x * 256 + t;
        for (; i + 3 * stride < tn4; i += 4 * stride) {
            float4 a0 = __ldcs(&p[i]);
            float4 a1 = __ldcs(&p[i + stride]);
            float4 a2 = __ldcs(&p[i + 2 * stride]);
            float4 a3 = __ldcs(&p[i + 3 * stride]);
            __stcs(&q[i], a0);
            __stcs(&q[i + stride], a1);
            __stcs(&q[i + 2 * stride], a2);
            __stcs(&q[i + 3 * stride], a3);
        }
        for (; i < tn4; i += stride) __stcs(&q[i], __ldcs(&p[i]));
    }

    // ---- Phase C: wait for all hist arrivals, then build this channel's LUT
    if (t == 0) {
        while (*(volatile int*)&g_ticket != NCTAS) __nanosleep(128);
    }
    __syncthreads();
    __threadfence();

    {
        int* hist = s_hist[0];
        int* cum  = s_hist[1];
        int h = __ldcg(&g_hist[c][t]);
        hist[t] = h;
        cum[t]  = h;
        if (t == 0) s_lastnz = 0;
        __syncthreads();

        #pragma unroll
        for (int off = 1; off < NUM_BINS; off <<= 1) {
            int tmp = (t >= off) ? cum[t - off] : 0;
            __syncthreads();
            cum[t] += tmp;
            __syncthreads();
        }
        if (h > 0) atomicMax(&s_lastnz, t);
        __syncthreads();

        const int total = cum[NUM_BINS - 1];
        const int step  = (total - hist[s_lastnz]) / (NUM_BINS - 1);

        float outv;
        if (step == 0) {
            outv = (float)t;                    // identity when step==0
        } else {
            int l = (t == 0) ? 0 : (cum[t - 1] + (step >> 1)) / step;
            outv = (float)min(NUM_BINS - 1, max(0, l));
        }
        s_lut[t] = outv;
        __syncthreads();
    }

    // ---- Phase D: apply from smem bins (no global re-read of samples) ----
    {
        float4* q = (float4*)(out + (size_t)c * npx);
        int g = base + t;
        for (; g + 768 < end; g += 1024) {
            uint32_t w0 = s_bins[g - base];
            uint32_t w1 = s_bins[g - base + 256];
            uint32_t w2 = s_bins[g - base + 512];
            uint32_t w3 = s_bins[g - base + 768];
            float4 r0, r1, r2, r3;
            r0.x = s_lut[w0 & 255]; r0.y = s_lut[(w0 >> 8) & 255];
            r0.z = s_lut[(w0 >> 16) & 255]; r0.w = s_lut[w0 >> 24];
            r1.x = s_lut[w1 & 255]; r1.y = s_lut[(w1 >> 8) & 255];
            r1.z = s_lut[(w1 >> 16) & 255]; r1.w = s_lut[w1 >> 24];
            r2.x = s_lut[w2 & 255]; r2.y = s_lut[(w2 >> 8) & 255];
            r2.z = s_lut[(w2 >> 16) & 255]; r2.w = s_lut[w2 >> 24];
            r3.x = s_lut[w3 & 255]; r3.y = s_lut[(w3 >> 8) & 255];
            r3.z = s_lut[(w3 >> 16) & 255]; r3.w = s_lut[w3 >> 24];
            __stcs(&q[g], r0);
            __stcs(&q[g + 256], r1);
            __stcs(&q[g + 512], r2);
            __stcs(&q[g + 768], r3);
        }
        for (; g < end; g += 256) {
            uint32_t w = s_bins[g - base];
            float4 r;
            r.x = s_lut[w & 255];
            r.y = s_lut[(w >> 8) & 255];
            r.z = s_lut[(w >> 16) & 255];
            r.w = s_lut[w >> 24];
            __stcs(&q[g], r);
        }
    }

    // ---- reset shared state for next graph replay (last-done CTA) ----
    __syncthreads();
    __shared__ int s_last;
    if (t == 0) {
        int d = atomicAdd(&g_done, 1);
        s_last = (d == NCTAS - 1);
    }
    __syncthreads();
    if (s_last) {
        g_hist[0][t] = 0;
        g_hist[1][t] = 0;
        g_hist[2][t] = 0;
        if (t == 0) { g_ticket = 0; g_done = 0; }
    }
}

extern "C" void kernel_launch(void* const* d_in, const int* in_sizes, int n_in,
                              void* d_out, int out_size) {
    const float* img = (const float*)d_in[0];
    float* out = (float*)d_out;
    const int npx = in_sizes[0] / NCH_TOTAL;   // 2048*4096

    equalize_fused_kernel<<<NCTAS, 256>>>(img, out, npx);
}